// round 1
// baseline (speedup 1.0000x reference)
#include <cuda_runtime.h>
#include <math_constants.h>

#define BB 32
#define CC 1024
#define HW 784
#define NF4 196          // HW/4
#define REDU 64
#define TD 768
#define AD 256
#define NCHUNK 16        // c-chunks for scores pass (64 channels each)

// ---- scratch (device globals; no allocation allowed) ----
__device__ float d_avg[BB*CC];
__device__ float d_maxv[BB*CC];
__device__ float d_chattn[BB*CC];
__device__ float d_g[BB*CC];
__device__ float d_xa[BB*CC];
__device__ float d_partial[BB*NCHUNK*HW];
__device__ float d_wsm[BB*HW];
__device__ float d_s[BB];

__device__ __forceinline__ float warp_sum(float v){
  #pragma unroll
  for (int o=16;o;o>>=1) v += __shfl_xor_sync(0xffffffffu, v, o);
  return v;
}
__device__ __forceinline__ float warp_max(float v){
  #pragma unroll
  for (int o=16;o;o>>=1) v = fmaxf(v, __shfl_xor_sync(0xffffffffu, v, o));
  return v;
}

// ---------------------------------------------------------------------------
// K1: per (b,c) row, mean + max over 784 spatial elements. Warp per row.
// ---------------------------------------------------------------------------
__global__ void k1_reduce(const float* __restrict__ x){
  int warp = threadIdx.x>>5, lane = threadIdx.x&31;
  int row = blockIdx.x*8 + warp;                 // 0..32767
  const float4* xr = (const float4*)(x + (size_t)row*HW);
  float s = 0.f, m = -CUDART_INF_F;
  #pragma unroll 2
  for (int i=lane; i<NF4; i+=32){
    float4 v = xr[i];
    s += (v.x+v.y)+(v.z+v.w);
    m = fmaxf(m, fmaxf(fmaxf(v.x,v.y), fmaxf(v.z,v.w)));
  }
  s = warp_sum(s); m = warp_max(m);
  if (lane==0){ d_avg[row] = s*(1.f/(float)HW); d_maxv[row] = m; }
}

// ---------------------------------------------------------------------------
// K2: per batch b — channel-attention MLP, q = tf@wq^T, qk = q@wk,
//     g[b,c] = qk[c]*ch_attn[c]/16.  One block per b, 256 threads.
// ---------------------------------------------------------------------------
__global__ void k2_prep(const float* __restrict__ tf, const float* __restrict__ w1,
                        const float* __restrict__ w2, const float* __restrict__ wq,
                        const float* __restrict__ wk){
  int b = blockIdx.x, tid = threadIdx.x, warp = tid>>5, lane = tid&31;
  __shared__ float s_avg[CC], s_max[CC], s_hs[REDU], s_tf[TD], s_q[AD];
  #pragma unroll
  for (int j=0;j<4;j++){ int c = tid + 256*j; s_avg[c] = d_avg[b*CC+c]; s_max[c] = d_maxv[b*CC+c]; }
  for (int k=tid;k<TD;k+=256) s_tf[k] = tf[b*TD+k];
  __syncthreads();

  // hidden layer: 64 rows, warp handles 8 rows
  for (int r = warp*8; r < warp*8+8; r++){
    const float* w1r = w1 + r*CC;
    float sa=0.f, sm=0.f;
    #pragma unroll 4
    for (int i=lane;i<CC;i+=32){ float wv_ = w1r[i]; sa += wv_*s_avg[i]; sm += wv_*s_max[i]; }
    sa = warp_sum(sa); sm = warp_sum(sm);
    if (lane==0) s_hs[r] = fmaxf(sa,0.f)+fmaxf(sm,0.f);
  }
  // q[a] = dot(tf, wq[a,:]) — warp handles 32 a's
  for (int j=0;j<32;j++){
    int a = warp*32 + j;
    const float* wqr = wq + a*TD;
    float acc=0.f;
    #pragma unroll 4
    for (int i=lane;i<TD;i+=32) acc += wqr[i]*s_tf[i];
    acc = warp_sum(acc);
    if (lane==0) s_q[a]=acc;
  }
  __syncthreads();

  // ch_attn + qk + g: each thread owns 4 channels
  #pragma unroll
  for (int j=0;j<4;j++){
    int c = tid + 256*j;
    float acc = 0.f;
    const float* w2r = w2 + c*REDU;
    #pragma unroll
    for (int r=0;r<REDU;r++) acc += s_hs[r]*w2r[r];
    float ch = 1.f/(1.f+__expf(-acc));
    d_chattn[b*CC+c] = ch;
    float qk = 0.f;
    #pragma unroll 4
    for (int a=0;a<AD;a++) qk += s_q[a]*wk[a*CC + c];
    d_g[b*CC+c] = qk * ch * 0.0625f;   // /sqrt(256)
  }
}

// ---------------------------------------------------------------------------
// K3: partial scores. Block (chunk, b) covers 64 channels; thread owns 3-4 n's.
//     partial[b,chunk,n] = sum over 64 channels of g[c]*x[b,c,n]
// ---------------------------------------------------------------------------
__global__ void k3_scores(const float* __restrict__ x){
  int b = blockIdx.y, chunk = blockIdx.x, tid = threadIdx.x;
  int c0 = chunk*64;
  __shared__ float sg[64];
  if (tid<64) sg[tid] = d_g[b*CC + c0 + tid];
  __syncthreads();
  float a0=0.f,a1=0.f,a2=0.f,a3=0.f;
  const float* xb = x + ((size_t)b*CC + c0)*HW;
  bool has4 = tid < (HW-768);    // tid < 16
  #pragma unroll 4
  for (int c=0;c<64;c++){
    const float* xr = xb + (size_t)c*HW;
    float gc = sg[c];
    a0 += gc*xr[tid];
    a1 += gc*xr[tid+256];
    a2 += gc*xr[tid+512];
    if (has4) a3 += gc*xr[tid+768];
  }
  float* p = d_partial + ((size_t)b*NCHUNK + chunk)*HW;
  p[tid]=a0; p[tid+256]=a1; p[tid+512]=a2; if (has4) p[tid+768]=a3;
}

// ---------------------------------------------------------------------------
// K4: reduce partials + softmax over n=784. One block per b.
// ---------------------------------------------------------------------------
__global__ void k4_softmax(){
  int b=blockIdx.x, tid=threadIdx.x, warp=tid>>5, lane=tid&31;
  __shared__ float sc[HW];
  __shared__ float redm[8], reds[8], bcast[2];
  for (int n=tid;n<HW;n+=256){
    float s=0.f;
    #pragma unroll
    for (int k=0;k<NCHUNK;k++) s += d_partial[((size_t)b*NCHUNK+k)*HW+n];
    sc[n]=s;
  }
  __syncthreads();
  float m=-CUDART_INF_F;
  for (int n=tid;n<HW;n+=256) m = fmaxf(m, sc[n]);
  m = warp_max(m);
  if (lane==0) redm[warp]=m;
  __syncthreads();
  if (tid==0){ float mm=redm[0]; for(int i=1;i<8;i++) mm=fmaxf(mm,redm[i]); bcast[0]=mm; }
  __syncthreads();
  float mm = bcast[0];
  float s=0.f;
  for (int n=tid;n<HW;n+=256){ float e = __expf(sc[n]-mm); sc[n]=e; s+=e; }
  s = warp_sum(s);
  if (lane==0) reds[warp]=s;
  __syncthreads();
  if (tid==0){ float t=0.f; for(int i=0;i<8;i++) t+=reds[i]; bcast[1]=1.f/t; }
  __syncthreads();
  float inv = bcast[1];
  for (int n=tid;n<HW;n+=256) d_wsm[b*HW+n] = sc[n]*inv;
}

// ---------------------------------------------------------------------------
// K5: xa[b,c] = ch_attn[b,c] * dot(attn_w[b,:], x[b,c,:]). Warp per row.
// ---------------------------------------------------------------------------
__global__ void k5_xa(const float* __restrict__ x){
  int warp=threadIdx.x>>5, lane=threadIdx.x&31;
  int row = blockIdx.x*8+warp;
  int b = row>>10;
  const float4* xr=(const float4*)(x+(size_t)row*HW);
  const float4* wr=(const float4*)(d_wsm + (size_t)b*HW);
  float acc=0.f;
  #pragma unroll 2
  for (int i=lane;i<NF4;i+=32){
    float4 v=xr[i], w=wr[i];
    acc += v.x*w.x+v.y*w.y+v.z*w.z+v.w*w.w;
  }
  acc = warp_sum(acc);
  if (lane==0) d_xa[row] = acc * d_chattn[row];
}

// ---------------------------------------------------------------------------
// K6: attended = wv @ xa ; s[b] = sigmoid(wo . attended); write out2 broadcast.
// ---------------------------------------------------------------------------
__global__ void k6_final(const float* __restrict__ wv, const float* __restrict__ wo,
                         float* __restrict__ out2){
  int b=blockIdx.x, tid=threadIdx.x, warp=tid>>5, lane=tid&31;
  __shared__ float s_xa[CC]; __shared__ float red[8]; __shared__ float s_sv;
  #pragma unroll
  for (int j=0;j<4;j++){ int c=tid+256*j; s_xa[c]=d_xa[b*CC+c]; }
  __syncthreads();
  float wpart=0.f;
  for (int j=0;j<32;j++){
    int a = warp*32+j;
    const float* wvr = wv + a*CC;
    float acc=0.f;
    #pragma unroll 4
    for (int i=lane;i<CC;i+=32) acc += wvr[i]*s_xa[i];
    acc = warp_sum(acc);
    wpart += acc * wo[a];      // identical on all lanes; lane0's copy is used
  }
  if (lane==0) red[warp]=wpart;
  __syncthreads();
  if (tid==0){
    float t=0.f; for(int i=0;i<8;i++) t+=red[i];
    float sv = 1.f/(1.f+__expf(-t));
    d_s[b]=sv; s_sv=sv;
  }
  __syncthreads();
  float sv = s_sv;
  if (out2){
    for (int n=tid;n<HW;n+=256) out2[b*HW+n]=sv;
  }
}

// ---------------------------------------------------------------------------
// K7: out[b,c,:] = x[b,c,:] * ch_attn[b,c] * s[b]. Warp per row, float4.
// ---------------------------------------------------------------------------
__global__ void k7_out(const float* __restrict__ x, float* __restrict__ out){
  int warp=threadIdx.x>>5, lane=threadIdx.x&31;
  int row=blockIdx.x*8+warp;
  float scale = d_chattn[row]*d_s[row>>10];
  const float4* xr=(const float4*)(x+(size_t)row*HW);
  float4* orow=(float4*)(out+(size_t)row*HW);
  #pragma unroll 2
  for (int i=lane;i<NF4;i+=32){
    float4 v=xr[i];
    v.x*=scale; v.y*=scale; v.z*=scale; v.w*=scale;
    orow[i]=v;
  }
}

extern "C" void kernel_launch(void* const* d_in, const int* in_sizes, int n_in,
                              void* d_out, int out_size){
  const float* x  = (const float*)d_in[0];
  const float* tf = (const float*)d_in[1];
  const float* w1 = (const float*)d_in[2];
  const float* w2 = (const float*)d_in[3];
  const float* wq = (const float*)d_in[4];
  const float* wk = (const float*)d_in[5];
  const float* wv = (const float*)d_in[6];
  const float* wo = (const float*)d_in[7];
  float* out = (float*)d_out;
  // Output = concat(flatten(x*spatial_attn), flatten(spatial_attn))
  long long main_elems = (long long)BB*CC*HW;
  float* out2 = ((long long)out_size >= main_elems + (long long)BB*HW)
                  ? out + main_elems : nullptr;

  k1_reduce <<<4096, 256>>>(x);
  k2_prep   <<<32,   256>>>(tf, w1, w2, wq, wk);
  k3_scores <<<dim3(NCHUNK, BB), 256>>>(x);
  k4_softmax<<<32,   256>>>();
  k5_xa     <<<4096, 256>>>(x);
  k6_final  <<<32,   256>>>(wv, wo, out2);
  k7_out    <<<4096, 256>>>(x, out);
}

// round 2
// speedup vs baseline: 3.9169x; 3.9169x over previous
#include <cuda_runtime.h>
#include <math_constants.h>

#define BB 32
#define CC 1024
#define HW 784
#define NF4 196          // HW/4
#define REDU 64
#define TD 768
#define AD 256
#define NCH 32           // c-chunks for scores pass (32 channels each)

// ---- scratch (device globals; no allocation allowed) ----
__device__ float d_avg[BB*CC];
__device__ float d_maxv[BB*CC];
__device__ float d_chattn[BB*CC];
__device__ float d_g[BB*CC];
__device__ float d_xa[BB*CC];
__device__ float d_hs[BB*REDU];
__device__ float d_q[BB*AD];
__device__ float d_u[CC];
__device__ float d_partial[BB*NCH*HW];
__device__ float d_wsm[BB*HW];
__device__ float d_s[BB];

__device__ __forceinline__ float warp_sum(float v){
  #pragma unroll
  for (int o=16;o;o>>=1) v += __shfl_xor_sync(0xffffffffu, v, o);
  return v;
}
__device__ __forceinline__ float warp_max(float v){
  #pragma unroll
  for (int o=16;o;o>>=1) v = fmaxf(v, __shfl_xor_sync(0xffffffffu, v, o));
  return v;
}

// ---------------------------------------------------------------------------
// kU: u[c] = sum_a wo[a]*wv[a,c]  (weights-only; enables k6 collapse)
// grid 4 x 256
// ---------------------------------------------------------------------------
__global__ void kU(const float* __restrict__ wv, const float* __restrict__ wo){
  __shared__ float s_wo[AD];
  int tid = threadIdx.x;
  if (tid < AD) s_wo[tid] = wo[tid];
  __syncthreads();
  int c = blockIdx.x*256 + tid;
  float acc = 0.f;
  #pragma unroll 8
  for (int a=0;a<AD;a++) acc += s_wo[a]*wv[a*CC + c];
  d_u[c] = acc;
}

// ---------------------------------------------------------------------------
// kQ: q[b,a] = dot(tf[b,:], wq[a,:]).  grid (8 achunk, 32 b), 256 thr.
// Each warp does 4 a's with 4-way ILP in one pass over 768.
// ---------------------------------------------------------------------------
__global__ void kQ(const float* __restrict__ tf, const float* __restrict__ wq){
  int chunk = blockIdx.x, b = blockIdx.y;
  int tid = threadIdx.x, warp = tid>>5, lane = tid&31;
  __shared__ float s_tf[TD];
  for (int i=tid;i<TD;i+=256) s_tf[i] = tf[b*TD+i];
  __syncthreads();
  int a0 = chunk*32 + warp*4;
  const float* w0 = wq + (a0+0)*TD;
  const float* w1 = wq + (a0+1)*TD;
  const float* w2 = wq + (a0+2)*TD;
  const float* w3 = wq + (a0+3)*TD;
  float acc0=0.f,acc1=0.f,acc2=0.f,acc3=0.f;
  #pragma unroll 4
  for (int i=lane;i<TD;i+=32){
    float t = s_tf[i];
    acc0 += w0[i]*t; acc1 += w1[i]*t; acc2 += w2[i]*t; acc3 += w3[i]*t;
  }
  acc0=warp_sum(acc0); acc1=warp_sum(acc1); acc2=warp_sum(acc2); acc3=warp_sum(acc3);
  if (lane==0){
    d_q[b*AD+a0+0]=acc0; d_q[b*AD+a0+1]=acc1;
    d_q[b*AD+a0+2]=acc2; d_q[b*AD+a0+3]=acc3;
  }
}

// ---------------------------------------------------------------------------
// K1: per (b,c) row: mean + max over 784. Warp per row. grid 4096 x 256.
// ---------------------------------------------------------------------------
__global__ void k1_reduce(const float* __restrict__ x){
  int warp = threadIdx.x>>5, lane = threadIdx.x&31;
  int row = blockIdx.x*8 + warp;
  const float4* xr = (const float4*)(x + (size_t)row*HW);
  float s = 0.f, m = -CUDART_INF_F;
  #pragma unroll 2
  for (int i=lane; i<NF4; i+=32){
    float4 v = xr[i];
    s += (v.x+v.y)+(v.z+v.w);
    m = fmaxf(m, fmaxf(fmaxf(v.x,v.y), fmaxf(v.z,v.w)));
  }
  s = warp_sum(s); m = warp_max(m);
  if (lane==0){ d_avg[row] = s*(1.f/(float)HW); d_maxv[row] = m; }
}

// ---------------------------------------------------------------------------
// K2h: hidden layer. grid (4 rchunk, 32 b), 256 thr. Warp does 2 rows w/ ILP.
// hs[r] = relu(w1[r]·avg) + relu(w1[r]·max)
// ---------------------------------------------------------------------------
__global__ void k2_hidden(const float* __restrict__ w1){
  int rchunk = blockIdx.x, b = blockIdx.y;
  int tid = threadIdx.x, warp = tid>>5, lane = tid&31;
  __shared__ float s_avg[CC], s_max[CC];
  #pragma unroll
  for (int j=0;j<4;j++){ int c=tid+256*j; s_avg[c]=d_avg[b*CC+c]; s_max[c]=d_maxv[b*CC+c]; }
  __syncthreads();
  int r0 = rchunk*16 + warp*2;
  const float* wr0 = w1 + (size_t)r0*CC;
  const float* wr1 = wr0 + CC;
  float a0=0.f,m0=0.f,a1=0.f,m1=0.f;
  #pragma unroll 4
  for (int i=lane;i<CC;i+=32){
    float va=s_avg[i], vm=s_max[i];
    float w0=wr0[i], w1v=wr1[i];
    a0+=w0*va; m0+=w0*vm; a1+=w1v*va; m1+=w1v*vm;
  }
  a0=warp_sum(a0); m0=warp_sum(m0); a1=warp_sum(a1); m1=warp_sum(m1);
  if (lane==0){
    d_hs[b*REDU+r0  ] = fmaxf(a0,0.f)+fmaxf(m0,0.f);
    d_hs[b*REDU+r0+1] = fmaxf(a1,0.f)+fmaxf(m1,0.f);
  }
}

// ---------------------------------------------------------------------------
// K2cg: ch_attn + g. grid (4 cchunk, 32 b), 256 thr, thread per channel.
// ---------------------------------------------------------------------------
__global__ void k2_chg(const float* __restrict__ w2, const float* __restrict__ wk){
  int cchunk = blockIdx.x, b = blockIdx.y, tid = threadIdx.x;
  __shared__ float s_hs[REDU];
  __shared__ float s_q[AD];
  if (tid < REDU) s_hs[tid] = d_hs[b*REDU+tid];
  if (tid >= 256-AD) ;  // noop
  if (tid < AD) s_q[tid] = d_q[b*AD+tid];
  __syncthreads();
  int c = cchunk*256 + tid;
  // mlp layer2: thread-private contiguous row of w2 (64 floats = 16 float4)
  const float4* w2v = (const float4*)(w2 + (size_t)c*REDU);
  float acc = 0.f;
  #pragma unroll
  for (int r4=0;r4<REDU/4;r4++){
    float4 wv4 = w2v[r4];
    acc += wv4.x*s_hs[r4*4+0] + wv4.y*s_hs[r4*4+1]
         + wv4.z*s_hs[r4*4+2] + wv4.w*s_hs[r4*4+3];
  }
  float ch = 1.f/(1.f+__expf(-acc));
  d_chattn[b*CC+c] = ch;
  // qk[c] = sum_a q[a]*wk[a,c]  (coalesced across threads)
  float qk = 0.f;
  #pragma unroll 8
  for (int a=0;a<AD;a++) qk += s_q[a]*wk[a*CC + c];
  d_g[b*CC+c] = qk * ch * 0.0625f;   // /sqrt(256)
}

// ---------------------------------------------------------------------------
// K3: partial scores, float4. grid (32 chunk, 32 b), 224 thr (196 active).
// partial[b,chunk,n] = sum over 32 channels of g[c]*x[b,c,n]
// ---------------------------------------------------------------------------
__global__ void k3_scores(const float* __restrict__ x){
  int chunk = blockIdx.x, b = blockIdx.y, tid = threadIdx.x;
  __shared__ float sg[32];
  if (tid<32) sg[tid] = d_g[b*CC + chunk*32 + tid];
  __syncthreads();
  if (tid >= NF4) return;
  const float4* xb4 = (const float4*)(x + ((size_t)b*CC + chunk*32)*HW);
  float4 acc = make_float4(0.f,0.f,0.f,0.f);
  #pragma unroll 8
  for (int c=0;c<32;c++){
    float4 v = xb4[c*NF4 + tid];
    float gc = sg[c];
    acc.x += gc*v.x; acc.y += gc*v.y; acc.z += gc*v.z; acc.w += gc*v.w;
  }
  float4* p4 = (float4*)(d_partial + ((size_t)b*NCH + chunk)*HW);
  p4[tid] = acc;
}

// ---------------------------------------------------------------------------
// K4: reduce 32 partials + softmax over 784. grid 32, 800 thr (784 active).
// ---------------------------------------------------------------------------
__global__ void k4_softmax(){
  int b=blockIdx.x, tid=threadIdx.x, warp=tid>>5, lane=tid&31;
  __shared__ float red[32], bcast[2];
  bool act = tid < HW;
  float s = 0.f;
  if (act){
    #pragma unroll 8
    for (int k=0;k<NCH;k++) s += d_partial[((size_t)b*NCH+k)*HW + tid];
  }
  // block max
  float m = act ? s : -CUDART_INF_F;
  m = warp_max(m);
  if (lane==0) red[warp]=m;
  __syncthreads();
  if (tid==0){ float mm=red[0]; for(int i=1;i<25;i++) mm=fmaxf(mm,red[i]); bcast[0]=mm; }
  __syncthreads();
  float mm = bcast[0];
  float e = act ? __expf(s-mm) : 0.f;
  float t = warp_sum(e);
  __syncthreads();
  if (lane==0) red[warp]=t;
  __syncthreads();
  if (tid==0){ float tt=0.f; for(int i=0;i<25;i++) tt+=red[i]; bcast[1]=1.f/tt; }
  __syncthreads();
  if (act) d_wsm[b*HW+tid] = e*bcast[1];
}

// ---------------------------------------------------------------------------
// K5: xa[b,c] = ch_attn[b,c] * dot(attn_w[b,:], x[b,c,:]). Warp per row.
// ---------------------------------------------------------------------------
__global__ void k5_xa(const float* __restrict__ x){
  int warp=threadIdx.x>>5, lane=threadIdx.x&31;
  int row = blockIdx.x*8+warp;
  int b = row>>10;
  const float4* xr=(const float4*)(x+(size_t)row*HW);
  const float4* wr=(const float4*)(d_wsm + (size_t)b*HW);
  float acc=0.f;
  #pragma unroll 2
  for (int i=lane;i<NF4;i+=32){
    float4 v=xr[i], w=wr[i];
    acc += v.x*w.x+v.y*w.y+v.z*w.z+v.w*w.w;
  }
  acc = warp_sum(acc);
  if (lane==0) d_xa[row] = acc * d_chattn[row];
}

// ---------------------------------------------------------------------------
// K6: s[b] = sigmoid(u · xa[b]); write out2 broadcast. One block, 1024 thr.
// ---------------------------------------------------------------------------
__global__ void k6_final(float* __restrict__ out2){
  int tid=threadIdx.x, warp=tid>>5, lane=tid&31;  // warp = b
  __shared__ float ss[BB];
  const float4* u4  = (const float4*)d_u;
  const float4* xa4 = (const float4*)(d_xa + (size_t)warp*CC);
  float acc=0.f;
  #pragma unroll
  for (int k=0;k<8;k++){
    int i = lane + 32*k;
    float4 u=u4[i], v=xa4[i];
    acc += u.x*v.x+u.y*v.y+u.z*v.z+u.w*v.w;
  }
  acc = warp_sum(acc);
  if (lane==0){
    float sv = 1.f/(1.f+__expf(-acc));
    d_s[warp]=sv; ss[warp]=sv;
  }
  __syncthreads();
  if (out2){
    for (int idx=tid; idx<BB*HW; idx+=1024)
      out2[idx] = ss[idx/HW];
  }
}

// ---------------------------------------------------------------------------
// K7: out[b,c,:] = x[b,c,:] * ch_attn[b,c] * s[b]. Warp per row, float4.
// ---------------------------------------------------------------------------
__global__ void k7_out(const float* __restrict__ x, float* __restrict__ out){
  int warp=threadIdx.x>>5, lane=threadIdx.x&31;
  int row=blockIdx.x*8+warp;
  float scale = d_chattn[row]*d_s[row>>10];
  const float4* xr=(const float4*)(x+(size_t)row*HW);
  float4* orow=(float4*)(out+(size_t)row*HW);
  #pragma unroll 2
  for (int i=lane;i<NF4;i+=32){
    float4 v=xr[i];
    v.x*=scale; v.y*=scale; v.z*=scale; v.w*=scale;
    orow[i]=v;
  }
}

extern "C" void kernel_launch(void* const* d_in, const int* in_sizes, int n_in,
                              void* d_out, int out_size){
  const float* x  = (const float*)d_in[0];
  const float* tf = (const float*)d_in[1];
  const float* w1 = (const float*)d_in[2];
  const float* w2 = (const float*)d_in[3];
  const float* wq = (const float*)d_in[4];
  const float* wk = (const float*)d_in[5];
  const float* wv = (const float*)d_in[6];
  const float* wo = (const float*)d_in[7];
  float* out = (float*)d_out;
  long long main_elems = (long long)BB*CC*HW;
  float* out2 = ((long long)out_size >= main_elems + (long long)BB*HW)
                  ? out + main_elems : nullptr;

  kU        <<<4, 256>>>(wv, wo);
  kQ        <<<dim3(8, BB), 256>>>(tf, wq);
  k1_reduce <<<4096, 256>>>(x);
  k2_hidden <<<dim3(4, BB), 256>>>(w1);
  k2_chg    <<<dim3(4, BB), 256>>>(w2, wk);
  k3_scores <<<dim3(NCH, BB), 224>>>(x);
  k4_softmax<<<BB, 800>>>();
  k5_xa     <<<4096, 256>>>(x);
  k6_final  <<<1, 1024>>>(out2);
  k7_out    <<<4096, 256>>>(x, out);
}